// round 10
// baseline (speedup 1.0000x reference)
#include <cuda_runtime.h>
#include <cstdint>

#define ZB 2
#define NPTS 4096
#define KNN 30
#define DMODEL 128
#define NEDGE (ZB*NPTS*KNN)
#define ASTRA 72
#define KROWS 32

typedef unsigned long long ull;

__device__ int    g_Kidx[NEDGE];
__device__ float  g_g1[DMODEL];
__device__ float  g_c0[DMODEL];
__device__ float2 g_Bfrag[4*8*16*32];   // [qt][k8q][nf][lane] -> (b0,b1)

__device__ __forceinline__ void mma8(float c[4], uint32_t a0, uint32_t a1, uint32_t a2, uint32_t a3,
                                     uint32_t b0, uint32_t b1) {
    asm("mma.sync.aligned.m16n8k8.row.col.f32.tf32.tf32.f32 "
        "{%0,%1,%2,%3},{%4,%5,%6,%7},{%8,%9},{%0,%1,%2,%3};"
        : "+f"(c[0]), "+f"(c[1]), "+f"(c[2]), "+f"(c[3])
        : "r"(a0), "r"(a1), "r"(a2), "r"(a3), "r"(b0), "r"(b1));
}

// --------------------------------------------------------------------------
// blocks 0-7: g_Bfrag[qt][k8q][nf][lane]; block 8: g1/c0 fold.
// mma-k t reads A phys offset f(t)=2*(t&3)+(t>>2) within each 8-block
// (a0=alo.x, a2=alo.y pairing) -> B logical must follow the same map.
__global__ __launch_bounds__(1024) void prep_kernel(
        const float* __restrict__ W, const float* __restrict__ gamma,
        const float* __restrict__ beta, const float* __restrict__ bias) {
    int tid = threadIdx.x;
    if (blockIdx.x < 8) {
#pragma unroll
        for (int u = 0; u < 2; ++u) {
            int p = blockIdx.x*2048 + u*1024 + tid;       // 0..16383
            int lane = p & 31, nf = (p >> 5) & 15, k8q = (p >> 9) & 7, qt = p >> 12;
            int n = nf*8 + (lane >> 2);
            float2 v;
#pragma unroll
            for (int h = 0; h < 2; ++h) {
                int t = (lane & 3) + 4*h;                 // mma-local k
                int fo = 2*(t & 3) + (t >> 2);            // phys offset read by A frag
                int p4 = k8q*8 + fo;                      // phys k within quarter
                int r = p4 >> 2, b = p4 & 3;              // phase A: phys = 4r + b
                int kL = (qt*4 + b)*16 + r;               // logical feature row
                float w = W[(size_t)kL*DMODEL + n] * gamma[kL];
                if (h == 0) v.x = w; else v.y = w;
            }
            g_Bfrag[p] = v;
        }
    } else {
        __shared__ float p1[8][DMODEL], p0[8][DMODEL];
        int g = tid >> 7, o = tid & 127;
        float a1 = 0.f, a0 = 0.f;
        int rb = g*32;
#pragma unroll 8
        for (int rr = 0; rr < 32; ++rr) {
            float w = W[(size_t)(rb+rr)*DMODEL + o];
            a1 = fmaf(gamma[rb+rr], w, a1);
            a0 = fmaf(beta[rb+rr],  w, a0);
        }
        p1[g][o] = a1; p0[g][o] = a0;
        __syncthreads();
        if (g == 0) {
            float s1 = 0.f, s0 = 0.f;
#pragma unroll
            for (int k = 0; k < 8; ++k) { s1 += p1[k][o]; s0 += p0[k][o]; }
            g_g1[o] = s1;
            g_c0[o] = s0 + bias[o];
        }
    }
}

// --------------------------------------------------------------------------
// 1 warp/row, warp-distributed top-30 with 32-bit (sq,idx) slot pairs.
__global__ __launch_bounds__(32*KROWS) void knn_kernel(
        const float* __restrict__ C, const unsigned char* __restrict__ nmask,
        float* __restrict__ koutf, float* __restrict__ moutf) {
    extern __shared__ float4 sh4[];            // NPTS
    int z = blockIdx.x / (NPTS/KROWS);
    int rowbase = (blockIdx.x % (NPTS/KROWS)) * KROWS;
    const float4* Cz4 = (const float4*)(C + (size_t)z*NPTS*12);
    for (int p = threadIdx.x; p < NPTS; p += 32*KROWS) {
        float4 a = Cz4[3*p], b = Cz4[3*p + 1];     // Ca = floats 3,4,5
        float x = a.w;
        if (nmask[z*NPTS + p]) x = __int_as_float(0x7fffffff);   // NaN-fold mask
        sh4[p] = make_float4(x, b.x, b.y, 0.f);
    }
    __syncthreads();
    int w = threadIdx.x >> 5, lane = threadIdx.x & 31;
    int i = rowbase + w;
    float4 qv = sh4[i];
    float qx = qv.x, qy = qv.y, qz = qv.z;

    unsigned slot_sq = 0xFFFFFFFFu;            // lane L: rank-L sq bits
    unsigned slot_idx = (unsigned)i;
    unsigned thrb = 0xFFFFFFFFu;

#pragma unroll 1
    for (int kb = 0; kb < NPTS/64; ++kb) {
        float4 p0 = sh4[kb*64 + lane], p1 = sh4[kb*64 + 32 + lane];
        float dx0 = __fsub_rn(p0.x, qx), dy0 = __fsub_rn(p0.y, qy), dz0 = __fsub_rn(p0.z, qz);
        float dx1 = __fsub_rn(p1.x, qx), dy1 = __fsub_rn(p1.y, qy), dz1 = __fsub_rn(p1.z, qz);
        float sq0 = __fadd_rn(__fadd_rn(__fmul_rn(dx0,dx0), __fmul_rn(dy0,dy0)), __fmul_rn(dz0,dz0));
        float sq1 = __fadd_rn(__fadd_rn(__fmul_rn(dx1,dx1), __fmul_rn(dy1,dy1)), __fmul_rn(dz1,dz1));
        unsigned q0 = __float_as_uint(sq0), q1 = __float_as_uint(sq1);
        unsigned bal0 = __ballot_sync(0xffffffffu, (sq0 > 0.f) && (q0 < thrb));
        unsigned bal1 = __ballot_sync(0xffffffffu, (sq1 > 0.f) && (q1 < thrb));
        if (bal0 | bal1) {
            while (bal0) {
                int s = __ffs(bal0) - 1; bal0 &= bal0 - 1;
                unsigned ksq = __shfl_sync(0xffffffffu, q0, s);
                unsigned kidx = (unsigned)(kb*64 + s);
                unsigned squp = __shfl_up_sync(0xffffffffu, slot_sq, 1);
                unsigned idup = __shfl_up_sync(0xffffffffu, slot_idx, 1);
                bool up = (squp > ksq) && (lane != 0);
                if (slot_sq > ksq) { slot_sq = up ? squp : ksq; slot_idx = up ? idup : kidx; }
            }
            while (bal1) {
                int s = __ffs(bal1) - 1; bal1 &= bal1 - 1;
                unsigned ksq = __shfl_sync(0xffffffffu, q1, s);
                unsigned kidx = (unsigned)(kb*64 + 32 + s);
                unsigned squp = __shfl_up_sync(0xffffffffu, slot_sq, 1);
                unsigned idup = __shfl_up_sync(0xffffffffu, slot_idx, 1);
                bool up = (squp > ksq) && (lane != 0);
                if (slot_sq > ksq) { slot_sq = up ? squp : ksq; slot_idx = up ? idup : kidx; }
            }
            thrb = __shfl_sync(0xffffffffu, slot_sq, 29);
        }
    }

    if (lane < KNN) {
        float sq = __uint_as_float(slot_sq);
        int jl = (int)slot_idx;
        bool mask = (nmask[z*NPTS + i] == 0) && (nmask[z*NPTS + jl] == 0)
                    && (sq > 0.f) && (sq < 144.f);          // NaN sentinel fails
        int kf = mask ? jl : i;
        int eidx = (z*NPTS + i)*KNN + lane;
        g_Kidx[eidx] = kf;
        koutf[eidx] = (float)kf;
        moutf[eidx] = mask ? 1.f : 0.f;
    }
}

// --------------------------------------------------------------------------
// 128 edges/block, K split into 4 quarters (query atom qt each). A 36.9KB +
// B-quarter 32KB staged in smem (B read from L2 once/block) -> 2 blocks/SM,
// GEMM inner loop pure LDS+HMMA. LN folded epilogue.
__global__ __launch_bounds__(512, 2) void edge_kernel(
        const float* __restrict__ C, const float* __restrict__ centers,
        float* __restrict__ Eout) {
    extern __shared__ float As[];                 // 128*ASTRA
    float* Bs  = As + 128*ASTRA;                  // 8192 floats (32KB)
    float* g1s = Bs + 8192;
    float* c0s = g1s + 128;
    float* mus = c0s + 128;
    float* rsg = mus + 128;

    int tid = threadIdx.x;
    if (tid < 128) { g1s[tid] = g_g1[tid]; c0s[tid] = g_c0[tid]; }

    float c0c = __ldg(centers), c15 = __ldg(centers + 15);
    float delta = (c15 - c0c) * (1.f/15.f);
    const float invS2 = 0.64f;
    float invdelta = __fdividef(1.f, delta);
    float sconst = __expf(-2.f*delta*delta*invS2);

    int m = tid >> 2, q = tid & 3;                // thread q = neighbor atom b
    int e = blockIdx.x*128 + m;
    int z = e / (NPTS*KNN);
    int i = (e - z*(NPTS*KNN)) / KNN;
    const float* pi = C + (size_t)z*NPTS*12 + (size_t)i*12;
    const float* pj = C + (size_t)z*NPTS*12 + (size_t)g_Kidx[e]*12;
    float bxc = pj[q*3], byc = pj[q*3 + 1], bzc = pj[q*3 + 2];
    float* Arow = As + m*ASTRA;

    int lane = tid & 31, wid = tid >> 5;
    int rowb = (wid >> 2)*32, nwid = wid & 3;
    int t4 = lane & 3, g4 = lane >> 2;
    float acc[2][4][4];
#pragma unroll
    for (int mf = 0; mf < 2; ++mf)
#pragma unroll
        for (int nf = 0; nf < 4; ++nf)
#pragma unroll
            for (int v = 0; v < 4; ++v) acc[mf][nf][v] = 0.f;
    float sum = 0.f, ssq = 0.f;

#pragma unroll 1
    for (int qt = 0; qt < 4; ++qt) {
        if (qt) __syncthreads();                  // prev GEMM done reading
        // ---- B fill: quarter table 4096 float2 = 2048 float4
        {
            const float4* src = (const float4*)(g_Bfrag + qt*4096);
            float4* dst = (float4*)Bs;
#pragma unroll
            for (int u = 0; u < 4; ++u) dst[u*512 + tid] = src[u*512 + tid];
        }
        // ---- phase A: dist(i atom qt, j atom q) -> 16 rbf at As[m][r*4+q]
        {
            float ax = pi[qt*3], ay = pi[qt*3 + 1], az = pi[qt*3 + 2];
            float dx = ax - bxc, dy = ay - byc, dz = az - bzc;
            float dsq = dx*dx + dy*dy + dz*dz;
            float d = sqrtf(dsq);
            int mi = __float2int_rn((d - c0c) * invdelta);
            mi = mi < 0 ? 0 : (mi > 15 ? 15 : mi);
            float u = d - fmaf((float)mi, delta, c0c);
            float vm = __expf(-u*u*invS2);
            float gup = __expf((2.f*delta*u - delta*delta)*invS2);
            float hdn = __fdividef(sconst, gup);
            Arow[mi*4 + q] = vm;
            sum += vm; ssq = fmaf(vm, vm, ssq);
            float v = vm, rat = gup;
            for (int r = mi+1; r < 16; ++r) {
                v *= rat; rat *= sconst;
                Arow[r*4 + q] = v;
                sum += v; ssq = fmaf(v, v, ssq);
            }
            v = vm; rat = hdn;
            for (int r = mi-1; r >= 0; --r) {
                v *= rat; rat *= sconst;
                Arow[r*4 + q] = v;
                sum += v; ssq = fmaf(v, v, ssq);
            }
        }
        if (qt == 3) {
            sum += __shfl_xor_sync(0xffffffffu, sum, 1);
            ssq += __shfl_xor_sync(0xffffffffu, ssq, 1);
            sum += __shfl_xor_sync(0xffffffffu, sum, 2);
            ssq += __shfl_xor_sync(0xffffffffu, ssq, 2);
            if (q == 0) {
                float mu = sum * (1.f/256.f);
                float var = ssq * (1.f/256.f) - mu*mu;
                mus[m] = mu;
                rsg[m] = rsqrtf(var + 1e-5f);
            }
        }
        __syncthreads();

        // ---- GEMM quarter: 8 k8q steps, B from smem
#pragma unroll 2
        for (int k8q = 0; k8q < 8; ++k8q) {
            float2 bf[4];
#pragma unroll
            for (int nf = 0; nf < 4; ++nf)
                bf[nf] = *(const float2*)&Bs[((k8q*16 + nwid*4 + nf)*32 + lane)*2];
#pragma unroll
            for (int mf = 0; mf < 2; ++mf) {
                int r0 = rowb + mf*16 + g4;
                float2 alo = *(const float2*)&As[r0*ASTRA + k8q*8 + 2*t4];
                float2 ahi = *(const float2*)&As[(r0+8)*ASTRA + k8q*8 + 2*t4];
                uint32_t a0 = __float_as_uint(alo.x), a2 = __float_as_uint(alo.y);
                uint32_t a1 = __float_as_uint(ahi.x), a3 = __float_as_uint(ahi.y);
#pragma unroll
                for (int nf = 0; nf < 4; ++nf)
                    mma8(acc[mf][nf], a0, a1, a2, a3,
                         __float_as_uint(bf[nf].x), __float_as_uint(bf[nf].y));
            }
        }
    }

    // ---- epilogue: out = rs*(acc - mu*g1) + c0
#pragma unroll
    for (int mf = 0; mf < 2; ++mf) {
        int r0 = rowb + mf*16 + g4;
        float mu0 = mus[r0],   rs0 = rsg[r0];
        float mu1 = mus[r0+8], rs1 = rsg[r0+8];
        float* o0 = Eout + ((size_t)(blockIdx.x*128 + r0))*DMODEL;
        float* o1 = o0 + 8*DMODEL;
#pragma unroll
        for (int nf = 0; nf < 4; ++nf) {
            int col = nwid*32 + nf*8 + 2*t4;
            float ga = g1s[col], gb = g1s[col+1];
            float ca = c0s[col], cb = c0s[col+1];
            float2 v0, v1;
            v0.x = fmaf(rs0, fmaf(-mu0, ga, acc[mf][nf][0]), ca);
            v0.y = fmaf(rs0, fmaf(-mu0, gb, acc[mf][nf][1]), cb);
            v1.x = fmaf(rs1, fmaf(-mu1, ga, acc[mf][nf][2]), ca);
            v1.y = fmaf(rs1, fmaf(-mu1, gb, acc[mf][nf][3]), cb);
            *(float2*)(o0 + col) = v0;
            *(float2*)(o1 + col) = v1;
        }
    }
}

// --------------------------------------------------------------------------
extern "C" void kernel_launch(void* const* d_in, const int* in_sizes, int n_in,
                              void* d_out, int out_size) {
    const float* C       = (const float*)d_in[0];
    const unsigned char* nm = (const unsigned char*)d_in[1];
    const float* centers = (const float*)d_in[2];
    const float* gamma   = (const float*)d_in[3];
    const float* beta    = (const float*)d_in[4];
    const float* W       = (const float*)d_in[5];
    const float* bias    = (const float*)d_in[6];
    float* out = (float*)d_out;
    float* kout = out + (size_t)NEDGE*DMODEL;
    float* mout = kout + NEDGE;

    size_t esm = (size_t)(128*ASTRA + 8192 + 4*128) * 4;   // 71680
    size_t ksm = (size_t)NPTS * 16;                        // 65536
    static bool attr_done = false;
    if (!attr_done) {
        cudaFuncSetAttribute(edge_kernel, cudaFuncAttributeMaxDynamicSharedMemorySize, (int)esm);
        cudaFuncSetAttribute(knn_kernel,  cudaFuncAttributeMaxDynamicSharedMemorySize, (int)ksm);
        attr_done = true;
    }

    knn_kernel<<<ZB*(NPTS/KROWS), 32*KROWS, ksm>>>(C, nm, kout, mout);
    prep_kernel<<<9, 1024>>>(W, gamma, beta, bias);
    edge_kernel<<<NEDGE/128, 512, esm>>>(C, centers, out);
}

// round 11
// speedup vs baseline: 1.0032x; 1.0032x over previous
#include <cuda_runtime.h>
#include <cstdint>

#define ZB 2
#define NPTS 4096
#define KNN 30
#define DMODEL 128
#define NEDGE (ZB*NPTS*KNN)
#define ASTRA 72
#define KROWS 32

typedef unsigned long long ull;

__device__ int    g_Kidx[NEDGE];
__device__ float  g_g1[DMODEL];
__device__ float  g_c0[DMODEL];
__device__ float2 g_Bfrag[4*8*16*32];   // [qt][k8q][nf][lane] -> (b0,b1)

__device__ __forceinline__ void mma8(float c[4], uint32_t a0, uint32_t a1, uint32_t a2, uint32_t a3,
                                     uint32_t b0, uint32_t b1) {
    asm("mma.sync.aligned.m16n8k8.row.col.f32.tf32.tf32.f32 "
        "{%0,%1,%2,%3},{%4,%5,%6,%7},{%8,%9},{%0,%1,%2,%3};"
        : "+f"(c[0]), "+f"(c[1]), "+f"(c[2]), "+f"(c[3])
        : "r"(a0), "r"(a1), "r"(a2), "r"(a3), "r"(b0), "r"(b1));
}

// --------------------------------------------------------------------------
// blocks 0-7: g_Bfrag[qt][k8q][nf][lane]; block 8: g1/c0 fold.
// mma-k t reads A phys offset f(t)=2*(t&3)+(t>>2) within each 8-block
// (a0=alo.x, a2=alo.y pairing) -> B logical must follow the same map.
__global__ __launch_bounds__(1024) void prep_kernel(
        const float* __restrict__ W, const float* __restrict__ gamma,
        const float* __restrict__ beta, const float* __restrict__ bias) {
    int tid = threadIdx.x;
    if (blockIdx.x < 8) {
#pragma unroll
        for (int u = 0; u < 2; ++u) {
            int p = blockIdx.x*2048 + u*1024 + tid;       // 0..16383
            int lane = p & 31, nf = (p >> 5) & 15, k8q = (p >> 9) & 7, qt = p >> 12;
            int n = nf*8 + (lane >> 2);
            float2 v;
#pragma unroll
            for (int h = 0; h < 2; ++h) {
                int t = (lane & 3) + 4*h;                 // mma-local k
                int fo = 2*(t & 3) + (t >> 2);            // phys offset read by A frag
                int p4 = k8q*8 + fo;                      // phys k within quarter
                int r = p4 >> 2, b = p4 & 3;              // phase A: phys = 4r + b
                int kL = (qt*4 + b)*16 + r;               // logical feature row
                float w = W[(size_t)kL*DMODEL + n] * gamma[kL];
                if (h == 0) v.x = w; else v.y = w;
            }
            g_Bfrag[p] = v;
        }
    } else {
        __shared__ float p1[8][DMODEL], p0[8][DMODEL];
        int g = tid >> 7, o = tid & 127;
        float a1 = 0.f, a0 = 0.f;
        int rb = g*32;
#pragma unroll 8
        for (int rr = 0; rr < 32; ++rr) {
            float w = W[(size_t)(rb+rr)*DMODEL + o];
            a1 = fmaf(gamma[rb+rr], w, a1);
            a0 = fmaf(beta[rb+rr],  w, a0);
        }
        p1[g][o] = a1; p0[g][o] = a0;
        __syncthreads();
        if (g == 0) {
            float s1 = 0.f, s0 = 0.f;
#pragma unroll
            for (int k = 0; k < 8; ++k) { s1 += p1[k][o]; s0 += p0[k][o]; }
            g_g1[o] = s1;
            g_c0[o] = s0 + bias[o];
        }
    }
}

// --------------------------------------------------------------------------
// 1 warp/row, warp-distributed top-30 with 32-bit (sq,idx) slot pairs.
__global__ __launch_bounds__(32*KROWS) void knn_kernel(
        const float* __restrict__ C, const unsigned char* __restrict__ nmask,
        float* __restrict__ koutf, float* __restrict__ moutf) {
    extern __shared__ float4 sh4[];            // NPTS
    int z = blockIdx.x / (NPTS/KROWS);
    int rowbase = (blockIdx.x % (NPTS/KROWS)) * KROWS;
    const float4* Cz4 = (const float4*)(C + (size_t)z*NPTS*12);
    for (int p = threadIdx.x; p < NPTS; p += 32*KROWS) {
        float4 a = Cz4[3*p], b = Cz4[3*p + 1];     // Ca = floats 3,4,5
        float x = a.w;
        if (nmask[z*NPTS + p]) x = __int_as_float(0x7fffffff);   // NaN-fold mask
        sh4[p] = make_float4(x, b.x, b.y, 0.f);
    }
    __syncthreads();
    int w = threadIdx.x >> 5, lane = threadIdx.x & 31;
    int i = rowbase + w;
    float4 qv = sh4[i];
    float qx = qv.x, qy = qv.y, qz = qv.z;

    unsigned slot_sq = 0xFFFFFFFFu;            // lane L: rank-L sq bits
    unsigned slot_idx = (unsigned)i;
    unsigned thrb = 0xFFFFFFFFu;

#pragma unroll 1
    for (int kb = 0; kb < NPTS/64; ++kb) {
        float4 p0 = sh4[kb*64 + lane], p1 = sh4[kb*64 + 32 + lane];
        float dx0 = __fsub_rn(p0.x, qx), dy0 = __fsub_rn(p0.y, qy), dz0 = __fsub_rn(p0.z, qz);
        float dx1 = __fsub_rn(p1.x, qx), dy1 = __fsub_rn(p1.y, qy), dz1 = __fsub_rn(p1.z, qz);
        float sq0 = __fadd_rn(__fadd_rn(__fmul_rn(dx0,dx0), __fmul_rn(dy0,dy0)), __fmul_rn(dz0,dz0));
        float sq1 = __fadd_rn(__fadd_rn(__fmul_rn(dx1,dx1), __fmul_rn(dy1,dy1)), __fmul_rn(dz1,dz1));
        unsigned q0 = __float_as_uint(sq0), q1 = __float_as_uint(sq1);
        unsigned bal0 = __ballot_sync(0xffffffffu, (sq0 > 0.f) && (q0 < thrb));
        unsigned bal1 = __ballot_sync(0xffffffffu, (sq1 > 0.f) && (q1 < thrb));
        if (bal0 | bal1) {
            while (bal0) {
                int s = __ffs(bal0) - 1; bal0 &= bal0 - 1;
                unsigned ksq = __shfl_sync(0xffffffffu, q0, s);
                unsigned kidx = (unsigned)(kb*64 + s);
                unsigned squp = __shfl_up_sync(0xffffffffu, slot_sq, 1);
                unsigned idup = __shfl_up_sync(0xffffffffu, slot_idx, 1);
                bool up = (squp > ksq) && (lane != 0);
                if (slot_sq > ksq) { slot_sq = up ? squp : ksq; slot_idx = up ? idup : kidx; }
            }
            while (bal1) {
                int s = __ffs(bal1) - 1; bal1 &= bal1 - 1;
                unsigned ksq = __shfl_sync(0xffffffffu, q1, s);
                unsigned kidx = (unsigned)(kb*64 + 32 + s);
                unsigned squp = __shfl_up_sync(0xffffffffu, slot_sq, 1);
                unsigned idup = __shfl_up_sync(0xffffffffu, slot_idx, 1);
                bool up = (squp > ksq) && (lane != 0);
                if (slot_sq > ksq) { slot_sq = up ? squp : ksq; slot_idx = up ? idup : kidx; }
            }
            thrb = __shfl_sync(0xffffffffu, slot_sq, 29);
        }
    }

    if (lane < KNN) {
        float sq = __uint_as_float(slot_sq);
        int jl = (int)slot_idx;
        bool mask = (nmask[z*NPTS + i] == 0) && (nmask[z*NPTS + jl] == 0)
                    && (sq > 0.f) && (sq < 144.f);          // NaN sentinel fails
        int kf = mask ? jl : i;
        int eidx = (z*NPTS + i)*KNN + lane;
        g_Kidx[eidx] = kf;
        koutf[eidx] = (float)kf;
        moutf[eidx] = mask ? 1.f : 0.f;
    }
}

// --------------------------------------------------------------------------
// 128 edges/block, K split into 4 quarters (query atom qt each). A 36.9KB +
// B-quarter 32KB staged in smem (B read from L2 once/block) -> 2 blocks/SM,
// GEMM inner loop pure LDS+HMMA. LN folded epilogue.
__global__ __launch_bounds__(512, 2) void edge_kernel(
        const float* __restrict__ C, const float* __restrict__ centers,
        float* __restrict__ Eout) {
    extern __shared__ float As[];                 // 128*ASTRA
    float* Bs  = As + 128*ASTRA;                  // 8192 floats (32KB)
    float* g1s = Bs + 8192;
    float* c0s = g1s + 128;
    float* mus = c0s + 128;
    float* rsg = mus + 128;

    int tid = threadIdx.x;
    if (tid < 128) { g1s[tid] = g_g1[tid]; c0s[tid] = g_c0[tid]; }

    float c0c = __ldg(centers), c15 = __ldg(centers + 15);
    float delta = (c15 - c0c) * (1.f/15.f);
    const float invS2 = 0.64f;
    float invdelta = __fdividef(1.f, delta);
    float sconst = __expf(-2.f*delta*delta*invS2);

    int m = tid >> 2, q = tid & 3;                // thread q = neighbor atom b
    int e = blockIdx.x*128 + m;
    int z = e / (NPTS*KNN);
    int i = (e - z*(NPTS*KNN)) / KNN;
    const float* pi = C + (size_t)z*NPTS*12 + (size_t)i*12;
    const float* pj = C + (size_t)z*NPTS*12 + (size_t)g_Kidx[e]*12;
    float bxc = pj[q*3], byc = pj[q*3 + 1], bzc = pj[q*3 + 2];
    float* Arow = As + m*ASTRA;

    int lane = tid & 31, wid = tid >> 5;
    int rowb = (wid >> 2)*32, nwid = wid & 3;
    int t4 = lane & 3, g4 = lane >> 2;
    float acc[2][4][4];
#pragma unroll
    for (int mf = 0; mf < 2; ++mf)
#pragma unroll
        for (int nf = 0; nf < 4; ++nf)
#pragma unroll
            for (int v = 0; v < 4; ++v) acc[mf][nf][v] = 0.f;
    float sum = 0.f, ssq = 0.f;

#pragma unroll 1
    for (int qt = 0; qt < 4; ++qt) {
        if (qt) __syncthreads();                  // prev GEMM done reading
        // ---- B fill: quarter table 4096 float2 = 2048 float4
        {
            const float4* src = (const float4*)(g_Bfrag + qt*4096);
            float4* dst = (float4*)Bs;
#pragma unroll
            for (int u = 0; u < 4; ++u) dst[u*512 + tid] = src[u*512 + tid];
        }
        // ---- phase A: dist(i atom qt, j atom q) -> 16 rbf at As[m][r*4+q]
        {
            float ax = pi[qt*3], ay = pi[qt*3 + 1], az = pi[qt*3 + 2];
            float dx = ax - bxc, dy = ay - byc, dz = az - bzc;
            float dsq = dx*dx + dy*dy + dz*dz;
            float d = sqrtf(dsq);
            int mi = __float2int_rn((d - c0c) * invdelta);
            mi = mi < 0 ? 0 : (mi > 15 ? 15 : mi);
            float u = d - fmaf((float)mi, delta, c0c);
            float vm = __expf(-u*u*invS2);
            float gup = __expf((2.f*delta*u - delta*delta)*invS2);
            float hdn = __fdividef(sconst, gup);
            Arow[mi*4 + q] = vm;
            sum += vm; ssq = fmaf(vm, vm, ssq);
            float v = vm, rat = gup;
            for (int r = mi+1; r < 16; ++r) {
                v *= rat; rat *= sconst;
                Arow[r*4 + q] = v;
                sum += v; ssq = fmaf(v, v, ssq);
            }
            v = vm; rat = hdn;
            for (int r = mi-1; r >= 0; --r) {
                v *= rat; rat *= sconst;
                Arow[r*4 + q] = v;
                sum += v; ssq = fmaf(v, v, ssq);
            }
        }
        if (qt == 3) {
            sum += __shfl_xor_sync(0xffffffffu, sum, 1);
            ssq += __shfl_xor_sync(0xffffffffu, ssq, 1);
            sum += __shfl_xor_sync(0xffffffffu, sum, 2);
            ssq += __shfl_xor_sync(0xffffffffu, ssq, 2);
            if (q == 0) {
                float mu = sum * (1.f/256.f);
                float var = ssq * (1.f/256.f) - mu*mu;
                mus[m] = mu;
                rsg[m] = rsqrtf(var + 1e-5f);
            }
        }
        __syncthreads();

        // ---- GEMM quarter: 8 k8q steps, B from smem
#pragma unroll 2
        for (int k8q = 0; k8q < 8; ++k8q) {
            float2 bf[4];
#pragma unroll
            for (int nf = 0; nf < 4; ++nf)
                bf[nf] = *(const float2*)&Bs[((k8q*16 + nwid*4 + nf)*32 + lane)*2];
#pragma unroll
            for (int mf = 0; mf < 2; ++mf) {
                int r0 = rowb + mf*16 + g4;
                float2 alo = *(const float2*)&As[r0*ASTRA + k8q*8 + 2*t4];
                float2 ahi = *(const float2*)&As[(r0+8)*ASTRA + k8q*8 + 2*t4];
                uint32_t a0 = __float_as_uint(alo.x), a2 = __float_as_uint(alo.y);
                uint32_t a1 = __float_as_uint(ahi.x), a3 = __float_as_uint(ahi.y);
#pragma unroll
                for (int nf = 0; nf < 4; ++nf)
                    mma8(acc[mf][nf], a0, a1, a2, a3,
                         __float_as_uint(bf[nf].x), __float_as_uint(bf[nf].y));
            }
        }
    }

    // ---- epilogue: out = rs*(acc - mu*g1) + c0
#pragma unroll
    for (int mf = 0; mf < 2; ++mf) {
        int r0 = rowb + mf*16 + g4;
        float mu0 = mus[r0],   rs0 = rsg[r0];
        float mu1 = mus[r0+8], rs1 = rsg[r0+8];
        float* o0 = Eout + ((size_t)(blockIdx.x*128 + r0))*DMODEL;
        float* o1 = o0 + 8*DMODEL;
#pragma unroll
        for (int nf = 0; nf < 4; ++nf) {
            int col = nwid*32 + nf*8 + 2*t4;
            float ga = g1s[col], gb = g1s[col+1];
            float ca = c0s[col], cb = c0s[col+1];
            float2 v0, v1;
            v0.x = fmaf(rs0, fmaf(-mu0, ga, acc[mf][nf][0]), ca);
            v0.y = fmaf(rs0, fmaf(-mu0, gb, acc[mf][nf][1]), cb);
            v1.x = fmaf(rs1, fmaf(-mu1, ga, acc[mf][nf][2]), ca);
            v1.y = fmaf(rs1, fmaf(-mu1, gb, acc[mf][nf][3]), cb);
            *(float2*)(o0 + col) = v0;
            *(float2*)(o1 + col) = v1;
        }
    }
}

// --------------------------------------------------------------------------
extern "C" void kernel_launch(void* const* d_in, const int* in_sizes, int n_in,
                              void* d_out, int out_size) {
    const float* C       = (const float*)d_in[0];
    const unsigned char* nm = (const unsigned char*)d_in[1];
    const float* centers = (const float*)d_in[2];
    const float* gamma   = (const float*)d_in[3];
    const float* beta    = (const float*)d_in[4];
    const float* W       = (const float*)d_in[5];
    const float* bias    = (const float*)d_in[6];
    float* out = (float*)d_out;
    float* kout = out + (size_t)NEDGE*DMODEL;
    float* mout = kout + NEDGE;

    size_t esm = (size_t)(128*ASTRA + 8192 + 4*128) * 4;   // 71680
    size_t ksm = (size_t)NPTS * 16;                        // 65536
    static bool attr_done = false;
    if (!attr_done) {
        cudaFuncSetAttribute(edge_kernel, cudaFuncAttributeMaxDynamicSharedMemorySize, (int)esm);
        cudaFuncSetAttribute(knn_kernel,  cudaFuncAttributeMaxDynamicSharedMemorySize, (int)ksm);
        attr_done = true;
    }

    knn_kernel<<<ZB*(NPTS/KROWS), 32*KROWS, ksm>>>(C, nm, kout, mout);
    prep_kernel<<<9, 1024>>>(W, gamma, beta, bias);
    edge_kernel<<<NEDGE/128, 512, esm>>>(C, centers, out);
}